// round 13
// baseline (speedup 1.0000x reference)
#include <cuda_runtime.h>
#include <math.h>
#include <float.h>
#include <stdint.h>

// ---------------- problem constants ----------------
#define BB     4
#define CIN    256
#define HH     200
#define WW     176
#define HWTOT  (HH*WW)          // 35200
#define AA     6
#define NCLS   4
#define NREG   7
#define NOUT   (NCLS*AA + NREG*AA)   // 66 (24 cls + 42 reg)
#define NANCH  (AA*HWTOT)       // 211200
#define KTOP   100
#define BOXSTRIDE 8             // padded box row in scratch

// ---------------- stage-1 tiling ----------------
#define TILE_HW  256
#define CK       16
#define NITER    (CIN/CK)       // 16
#define NTHREADS 352            // 11 warps
#define OT       6              // outputs per warp (11*6 = 66)
#define NPAIR    4              // hw PAIRS per thread (32 lanes * 4 pairs * 2 = 256)
#define ESM_STRIDE 67           // padded row stride for epilogue smem
#define WREGION  (TILE_HW*ESM_STRIDE)     // 17152 floats (>= 66*256 = 16896)
#define CHUNK_FLOATS (CK*TILE_HW)         // 4096
#define CHUNK_F4 (CHUNK_FLOATS/4)         // 1024
#define SMEM_FLOATS (WREGION + 2*CHUNK_FLOATS)
#define SMEM_BYTES  (SMEM_FLOATS*4)       // ~101 KB

// ---------------- top-k constants ----------------
#define NBINS   65536
#define CANDMAX 4096

// ---------------- device scratch (zero-initialized at module load) ----------------
__device__ float    g_scores[(size_t)BB*NANCH*NCLS];
__device__ float    g_boxes [(size_t)BB*NANCH*BOXSTRIDE];
__device__ float    g_maxs  [(size_t)BB*NANCH];
__device__ unsigned g_hist  [BB*NBINS];   // re-zeroed by select_kernel each run

// ---------------- cp.async helpers ----------------
__device__ __forceinline__ void cp16(uint32_t smem_addr, const void* gptr) {
    asm volatile("cp.async.ca.shared.global [%0], [%1], 16;"
                 :: "r"(smem_addr), "l"(gptr));
}
__device__ __forceinline__ void cp_commit() {
    asm volatile("cp.async.commit_group;");
}
template<int N> __device__ __forceinline__ void cp_wait() {
    asm volatile("cp.async.wait_group %0;" :: "n"(N));
}

// ---------------- packed f32x2 helpers (Blackwell sm_100+ base) ----------------
__device__ __forceinline__ void ffma2(unsigned long long& d,
                                      unsigned long long a,
                                      unsigned long long b) {
    asm("fma.rn.f32x2 %0, %1, %2, %0;" : "+l"(d) : "l"(a), "l"(b));
}
__device__ __forceinline__ unsigned long long pack_dup(float w) {
    unsigned long long r;
    asm("mov.b64 %0, {%1, %1};" : "=l"(r) : "f"(w));
    return r;
}
__device__ __forceinline__ float2 unpack2(unsigned long long v) {
    float2 f;
    asm("mov.b64 {%0, %1}, %2;" : "=f"(f.x), "=f"(f.y) : "l"(v));
    return f;
}

// ============================================================================
// Stage 1: fused 1x1-conv heads (GEMM via packed FFMA2) + softmax + decode + hist
// ============================================================================
__global__ __launch_bounds__(NTHREADS, 2)
void head_kernel(const float* __restrict__ x,
                 const float* __restrict__ cls_w, const float* __restrict__ cls_b,
                 const float* __restrict__ reg_w, const float* __restrict__ reg_b,
                 const float* __restrict__ anchors)
{
    extern __shared__ float sm[];
    float* wT  = sm;                 // [256][66] transposed weights (union with esm)
    float* esm = sm;                 // [256][67] epilogue tile (reuses wT region)
    float* xsA = sm + WREGION;       // buffer 0: [CK][256]
    float* xsB = xsA + CHUNK_FLOATS; // buffer 1

    const int b    = blockIdx.y;
    const int hw0  = blockIdx.x * TILE_HW;
    const int tid  = threadIdx.x;
    const int lane = tid & 31;
    const int wrp  = tid >> 5;       // 0..10
    const int obase = wrp * OT;

    const float* xb = x + (size_t)b * CIN * HWTOT;
    const uint32_t xsA_s = (uint32_t)__cvta_generic_to_shared(xsA);
    const uint32_t xsB_s = (uint32_t)__cvta_generic_to_shared(xsB);

    // issue async copy of chunk cc into a buffer
    auto issue_chunk = [&](int cc, float* dst, uint32_t dst_s) {
        for (int idx = tid; idx < CHUNK_F4; idx += NTHREADS) {
            int c   = idx >> 6;          // /64
            int f4  = idx & 63;
            int col = f4 * 4;
            if (hw0 + col < HWTOT) {
                cp16(dst_s + (uint32_t)(c*TILE_HW + col)*4,
                     xb + (size_t)(cc + c)*HWTOT + hw0 + col);
            } else {
                *(float4*)(dst + c*TILE_HW + col) = make_float4(0.f,0.f,0.f,0.f);
            }
        }
        cp_commit();
    };

    // prefetch chunk 0 into buffer A
    issue_chunk(0, xsA, xsA_s);

    // load combined weights transposed into smem: wT[c*66 + o]
    for (int idx = tid; idx < NOUT*CIN; idx += NTHREADS) {
        int o = idx >> 8;            // /256
        int c = idx & 255;
        float v = (o < NCLS*AA) ? cls_w[o*CIN + c] : reg_w[(o - NCLS*AA)*CIN + c];
        wT[c*NOUT + o] = v;
    }

    unsigned long long acc[OT][NPAIR];
    #pragma unroll
    for (int j = 0; j < OT; j++)
        #pragma unroll
        for (int p = 0; p < NPAIR; p++) acc[j][p] = 0ull;

    #pragma unroll 1
    for (int it = 0; it < NITER; it++) {
        const int cc = it * CK;
        float* cur = (it & 1) ? xsB : xsA;
        if (it + 1 < NITER) {
            if (it > 0) __syncthreads();   // everyone done computing on the other buffer
            float*   nxt   = (it & 1) ? xsA : xsB;
            uint32_t nxt_s = (it & 1) ? xsA_s : xsB_s;
            issue_chunk(cc + CK, nxt, nxt_s);
            cp_wait<1>();                  // current chunk complete
        } else {
            cp_wait<0>();
        }
        __syncthreads();                   // cp.async data + wT (first iter) visible

        #pragma unroll
        for (int c = 0; c < CK; c++) {
            // 4 pair-loads of x (LDS.64, conflict-free: lanes hit distinct banks)
            unsigned long long xp0 = *(const unsigned long long*)(cur + c*TILE_HW + 2*lane);
            unsigned long long xp1 = *(const unsigned long long*)(cur + c*TILE_HW + 2*lane + 64);
            unsigned long long xp2 = *(const unsigned long long*)(cur + c*TILE_HW + 2*lane + 128);
            unsigned long long xp3 = *(const unsigned long long*)(cur + c*TILE_HW + 2*lane + 192);
            const float* wrow = &wT[(cc + c)*NOUT + obase];
            // one packed weight live at a time -> minimal register pressure
            #pragma unroll
            for (int j = 0; j < OT; j++) {
                unsigned long long wj = pack_dup(wrow[j]);
                ffma2(acc[j][0], wj, xp0);
                ffma2(acc[j][1], wj, xp1);
                ffma2(acc[j][2], wj, xp2);
                ffma2(acc[j][3], wj, xp3);
            }
        }
    }

    __syncthreads();   // done reading wT; reuse region as esm

    // add bias, scatter accumulators into epilogue tile esm[hw][o]
    float bias[OT];
    #pragma unroll
    for (int j = 0; j < OT; j++) {
        int o = obase + j;
        bias[j] = (o < NCLS*AA) ? cls_b[o] : reg_b[o - NCLS*AA];
    }
    #pragma unroll
    for (int j = 0; j < OT; j++)
        #pragma unroll
        for (int p = 0; p < NPAIR; p++) {
            float2 v = unpack2(acc[j][p]);
            int m0 = 2*lane + 64*p;
            esm[(m0    )*ESM_STRIDE + obase + j] = v.x + bias[j];
            esm[(m0 + 1)*ESM_STRIDE + obase + j] = v.y + bias[j];
        }
    __syncthreads();

    // per-anchor epilogue: softmax + decode + store + warp-aggregated histogram
    for (int t = tid; t < TILE_HW*AA; t += NTHREADS) {
        int hwl = t / AA;
        int a   = t - hwl*AA;
        if (hw0 + hwl >= HWTOT) continue;
        int n = (hw0 + hwl)*AA + a;                 // anchor index within batch
        const float* e = esm + hwl*ESM_STRIDE;

        // softmax over 4 class logits (channel o = a*4 + c)
        float l0 = e[a*4+0], l1 = e[a*4+1], l2 = e[a*4+2], l3 = e[a*4+3];
        float m  = fmaxf(fmaxf(l0, l1), fmaxf(l2, l3));
        float e0 = expf(l0 - m), e1 = expf(l1 - m), e2 = expf(l2 - m), e3 = expf(l3 - m);
        float inv = 1.f / (e0 + e1 + e2 + e3);
        float p0 = e0*inv, p1 = e1*inv, p2 = e2*inv, p3 = e3*inv;

        size_t base = (size_t)b*NANCH + n;
        *(float4*)(g_scores + base*4) = make_float4(p0, p1, p2, p3);
        float mx = fmaxf(fmaxf(p1, p2), p3);
        g_maxs[base] = mx;

        // warp-aggregated histogram update
        unsigned bin  = __float_as_uint(mx) >> 16;
        unsigned amask = __activemask();
        unsigned peers = __match_any_sync(amask, bin);
        int leader = __ffs(peers) - 1;
        if ((tid & 31) == leader)
            atomicAdd(&g_hist[b*NBINS + bin], (unsigned)__popc(peers));

        // decode (channel o = 24 + a*7 + r); padded stride-8 vector stores
        const float* d  = e + NCLS*AA + a*NREG;
        const float* an = anchors + (size_t)n*NREG;
        float xa = an[0], ya = an[1], za = an[2];
        float dxa = an[3], dya = an[4], dza = an[5], ra = an[6];
        float diag = sqrtf(dxa*dxa + dya*dya);
        float* ob = g_boxes + base*BOXSTRIDE;
        float4 b0, b1;
        b0.x = fmaf(d[0], diag, xa);
        b0.y = fmaf(d[1], diag, ya);
        b0.z = fmaf(d[2], dza,  za);
        b0.w = expf(d[3]) * dxa;
        b1.x = expf(d[4]) * dya;
        b1.y = expf(d[5]) * dza;
        b1.z = d[6] + ra;
        b1.w = 0.f;
        *(float4*)(ob + 0) = b0;
        *(float4*)(ob + 4) = b1;
    }
}

// ============================================================================
// Stage 2: per-batch fused threshold-find + compact + sort + gather.
// Also re-zeros this batch's histogram slice for the next run (graph replay).
// ============================================================================
__global__ __launch_bounds__(1024)
void select_kernel(float* __restrict__ outS, float* __restrict__ outB)
{
    const int b   = blockIdx.x;
    const int tid = threadIdx.x;
    const int lane = tid & 31;
    const int wrp  = tid >> 5;

    __shared__ unsigned csum[1024];   // per-thread chunk sums (64 bins each)
    __shared__ unsigned wsum[32];     // per-warp sums (2048 bins each)
    __shared__ int      sThr;
    __shared__ int      sCnt;
    __shared__ float    sv[CANDMAX];
    __shared__ int      si[CANDMAX];

    // ---- phase 1: chunk sums of the 65536-bin histogram ----
    unsigned* h = g_hist + b*NBINS;
    {
        const uint4* h4 = (const uint4*)(h + tid*64);
        unsigned s = 0;
        #pragma unroll
        for (int k = 0; k < 16; k++) { uint4 v = h4[k]; s += v.x + v.y + v.z + v.w; }
        csum[tid] = s;
        unsigned ws = s;
        #pragma unroll
        for (int o = 16; o > 0; o >>= 1) ws += __shfl_down_sync(0xFFFFFFFFu, ws, o);
        if (lane == 0) wsum[wrp] = ws;
    }
    if (tid == 0) sCnt = 0;
    __syncthreads();

    // ---- phase 2: hierarchical threshold find ----
    if (tid == 0) {
        unsigned cum = 0;
        int w = 31;
        for (; w > 0; w--) { if (cum + wsum[w] >= (unsigned)KTOP) break; cum += wsum[w]; }
        int t = w*32 + 31;
        for (; t > w*32; t--) { if (cum + csum[t] >= (unsigned)KTOP) break; cum += csum[t]; }
        int thr = t*64;
        for (int k = 63; k >= 0; k--) {
            unsigned c = h[t*64 + k];
            if (cum + c >= (unsigned)KTOP) { thr = t*64 + k; break; }
            cum += c;
        }
        sThr = thr;
    }
    __syncthreads();

    // ---- phase 2b: hist consumed -> re-zero for next run ----
    {
        uint4* h4 = (uint4*)(h + tid*64);
        #pragma unroll
        for (int k = 0; k < 16; k++) h4[k] = make_uint4(0u,0u,0u,0u);
    }

    // ---- phase 3: compact candidates ----
    {
        const int thr = sThr;
        const float* mv = g_maxs + (size_t)b*NANCH;
        for (int i = tid; i < NANCH; i += 1024) {
            float v = mv[i];
            if ((int)(__float_as_uint(v) >> 16) >= thr) {
                int p = atomicAdd(&sCnt, 1);
                if (p < CANDMAX) { sv[p] = v; si[p] = i; }
            }
        }
    }
    __syncthreads();

    int cnt = sCnt;
    if (cnt > CANDMAX) cnt = CANDMAX;
    int p2 = 128;
    while (p2 < cnt) p2 <<= 1;
    for (int k = cnt + tid; k < p2; k += 1024) { sv[k] = -FLT_MAX; si[k] = 0x7FFFFFFF; }
    __syncthreads();

    // ---- phase 4: bitonic sort desc by (value, then ascending index) ----
    for (int k2 = 2; k2 <= p2; k2 <<= 1) {
        for (int j = k2 >> 1; j > 0; j >>= 1) {
            for (int i = tid; i < p2; i += 1024) {
                int ixj = i ^ j;
                if (ixj > i) {
                    float va = sv[i], vb = sv[ixj];
                    int   ia = si[i], ib = si[ixj];
                    bool a_below_b = (va < vb) || (va == vb && ia > ib);
                    bool up = ((i & k2) == 0);
                    if (up ? a_below_b : !a_below_b) {
                        sv[i] = vb; sv[ixj] = va; si[i] = ib; si[ixj] = ia;
                    }
                }
            }
            __syncthreads();
        }
    }

    // ---- phase 5: gather top-K ----
    if (tid < KTOP) {
        int k = tid;
        int n = si[k];
        size_t base = (size_t)b*NANCH + n;
        float4 s4 = *(const float4*)(g_scores + base*4);
        *(float4*)(outS + ((size_t)b*KTOP + k)*4) = s4;
        const float* bx = g_boxes + base*BOXSTRIDE;
        float4 b0 = *(const float4*)(bx + 0);
        float4 b1 = *(const float4*)(bx + 4);
        float* ob = outB + ((size_t)b*KTOP + k)*NREG;
        ob[0] = b0.x; ob[1] = b0.y; ob[2] = b0.z; ob[3] = b0.w;
        ob[4] = b1.x; ob[5] = b1.y; ob[6] = b1.z;
    }
}

// ============================================================================
extern "C" void kernel_launch(void* const* d_in, const int* in_sizes, int n_in,
                              void* d_out, int out_size)
{
    const float* x       = (const float*)d_in[0];
    const float* cls_w   = (const float*)d_in[1];
    const float* cls_b   = (const float*)d_in[2];
    const float* reg_w   = (const float*)d_in[3];
    const float* reg_b   = (const float*)d_in[4];
    const float* anchors = (const float*)d_in[5];

    float* outS = (float*)d_out;                 // [B, K, 4]
    float* outB = outS + (size_t)BB*KTOP*NCLS;   // [B, K, 7]

    cudaFuncSetAttribute(head_kernel, cudaFuncAttributeMaxDynamicSharedMemorySize, SMEM_BYTES);

    head_kernel<<<dim3((HWTOT + TILE_HW - 1)/TILE_HW, BB), NTHREADS, SMEM_BYTES>>>(
        x, cls_w, cls_b, reg_w, reg_b, anchors);
    select_kernel<<<BB, 1024>>>(outS, outB);
}

// round 14
// speedup vs baseline: 1.1832x; 1.1832x over previous
#include <cuda_runtime.h>
#include <math.h>
#include <float.h>
#include <stdint.h>

// ---------------- problem constants ----------------
#define BB     4
#define CIN    256
#define HH     200
#define WW     176
#define HWTOT  (HH*WW)          // 35200
#define AA     6
#define NCLS   4
#define NREG   7
#define NOUT   (NCLS*AA + NREG*AA)   // 66 (24 cls + 42 reg)
#define NANCH  (AA*HWTOT)       // 211200
#define KTOP   100
#define BOXSTRIDE 8             // padded box row in scratch

// ---------------- stage-1 tiling ----------------
#define TILE_HW  256
#define CK       16
#define NITER    (CIN/CK)       // 16
#define NTHREADS 352            // 11 warps
#define OT       6              // outputs per warp (11*6 = 66)
#define NPAIR    4              // hw PAIRS per thread (32 lanes * 4 pairs * 2 = 256)
#define ESM_STRIDE 67           // padded row stride for epilogue smem
#define WREGION  (TILE_HW*ESM_STRIDE)     // 17152 floats (>= 66*256 = 16896)
#define CHUNK_FLOATS (CK*TILE_HW)         // 4096
#define CHUNK_F4 (CHUNK_FLOATS/4)         // 1024
#define SMEM_FLOATS (WREGION + 2*CHUNK_FLOATS)
#define SMEM_BYTES  (SMEM_FLOATS*4)       // ~101 KB

// ---------------- top-k constants ----------------
#define NBINS   65536
#define CANDMAX 4096
#define CBLK    32              // compact blocks per batch
#define CSLICE  (NANCH/CBLK)    // 6600 anchors per compact block

// ---------------- device scratch (zero-initialized at module load) ----------------
__device__ float    g_scores[(size_t)BB*NANCH*NCLS];
__device__ float    g_boxes [(size_t)BB*NANCH*BOXSTRIDE];
__device__ float    g_maxs  [(size_t)BB*NANCH];
__device__ unsigned g_hist  [BB*NBINS];   // re-zeroed by compact_kernel each run
__device__ int      g_thr   [BB];
__device__ int      g_candCnt[BB];
__device__ float    g_candV [BB*CANDMAX];
__device__ int      g_candI [BB*CANDMAX];

// ---------------- cp.async helpers ----------------
__device__ __forceinline__ void cp16(uint32_t smem_addr, const void* gptr) {
    asm volatile("cp.async.ca.shared.global [%0], [%1], 16;"
                 :: "r"(smem_addr), "l"(gptr));
}
__device__ __forceinline__ void cp_commit() {
    asm volatile("cp.async.commit_group;");
}
template<int N> __device__ __forceinline__ void cp_wait() {
    asm volatile("cp.async.wait_group %0;" :: "n"(N));
}

// ---------------- packed f32x2 helpers (Blackwell sm_100+ base) ----------------
__device__ __forceinline__ void ffma2(unsigned long long& d,
                                      unsigned long long a,
                                      unsigned long long b) {
    asm("fma.rn.f32x2 %0, %1, %2, %0;" : "+l"(d) : "l"(a), "l"(b));
}
__device__ __forceinline__ unsigned long long pack_dup(float w) {
    unsigned long long r;
    asm("mov.b64 %0, {%1, %1};" : "=l"(r) : "f"(w));
    return r;
}
__device__ __forceinline__ float2 unpack2(unsigned long long v) {
    float2 f;
    asm("mov.b64 {%0, %1}, %2;" : "=f"(f.x), "=f"(f.y) : "l"(v));
    return f;
}

// ============================================================================
// Stage 1: fused 1x1-conv heads (GEMM via packed FFMA2) + softmax + decode + hist
// ============================================================================
__global__ __launch_bounds__(NTHREADS, 2)
void head_kernel(const float* __restrict__ x,
                 const float* __restrict__ cls_w, const float* __restrict__ cls_b,
                 const float* __restrict__ reg_w, const float* __restrict__ reg_b,
                 const float* __restrict__ anchors)
{
    extern __shared__ float sm[];
    float* wT  = sm;                 // [256][66] transposed weights (union with esm)
    float* esm = sm;                 // [256][67] epilogue tile (reuses wT region)
    float* xsA = sm + WREGION;       // buffer 0: [CK][256]
    float* xsB = xsA + CHUNK_FLOATS; // buffer 1

    const int b    = blockIdx.y;
    const int hw0  = blockIdx.x * TILE_HW;
    const int tid  = threadIdx.x;
    const int lane = tid & 31;
    const int wrp  = tid >> 5;       // 0..10
    const int obase = wrp * OT;

    const float* xb = x + (size_t)b * CIN * HWTOT;
    const uint32_t xsA_s = (uint32_t)__cvta_generic_to_shared(xsA);
    const uint32_t xsB_s = (uint32_t)__cvta_generic_to_shared(xsB);

    // issue async copy of chunk cc into a buffer
    auto issue_chunk = [&](int cc, float* dst, uint32_t dst_s) {
        for (int idx = tid; idx < CHUNK_F4; idx += NTHREADS) {
            int c   = idx >> 6;          // /64
            int f4  = idx & 63;
            int col = f4 * 4;
            if (hw0 + col < HWTOT) {
                cp16(dst_s + (uint32_t)(c*TILE_HW + col)*4,
                     xb + (size_t)(cc + c)*HWTOT + hw0 + col);
            } else {
                *(float4*)(dst + c*TILE_HW + col) = make_float4(0.f,0.f,0.f,0.f);
            }
        }
        cp_commit();
    };

    // prefetch chunk 0 into buffer A
    issue_chunk(0, xsA, xsA_s);

    // load combined weights transposed into smem: wT[c*66 + o]
    for (int idx = tid; idx < NOUT*CIN; idx += NTHREADS) {
        int o = idx >> 8;            // /256
        int c = idx & 255;
        float v = (o < NCLS*AA) ? cls_w[o*CIN + c] : reg_w[(o - NCLS*AA)*CIN + c];
        wT[c*NOUT + o] = v;
    }

    unsigned long long acc[OT][NPAIR];
    #pragma unroll
    for (int j = 0; j < OT; j++)
        #pragma unroll
        for (int p = 0; p < NPAIR; p++) acc[j][p] = 0ull;

    #pragma unroll 1
    for (int it = 0; it < NITER; it++) {
        const int cc = it * CK;
        float* cur = (it & 1) ? xsB : xsA;
        if (it + 1 < NITER) {
            if (it > 0) __syncthreads();   // everyone done computing on the other buffer
            float*   nxt   = (it & 1) ? xsA : xsB;
            uint32_t nxt_s = (it & 1) ? xsA_s : xsB_s;
            issue_chunk(cc + CK, nxt, nxt_s);
            cp_wait<1>();                  // current chunk complete
        } else {
            cp_wait<0>();
        }
        __syncthreads();                   // cp.async data + wT (first iter) visible

        #pragma unroll
        for (int c = 0; c < CK; c++) {
            // 4 pair-loads of x (LDS.64, conflict-free)
            unsigned long long xp0 = *(const unsigned long long*)(cur + c*TILE_HW + 2*lane);
            unsigned long long xp1 = *(const unsigned long long*)(cur + c*TILE_HW + 2*lane + 64);
            unsigned long long xp2 = *(const unsigned long long*)(cur + c*TILE_HW + 2*lane + 128);
            unsigned long long xp3 = *(const unsigned long long*)(cur + c*TILE_HW + 2*lane + 192);
            const float* wrow = &wT[(cc + c)*NOUT + obase];
            // one packed weight live at a time -> minimal register pressure
            #pragma unroll
            for (int j = 0; j < OT; j++) {
                unsigned long long wj = pack_dup(wrow[j]);
                ffma2(acc[j][0], wj, xp0);
                ffma2(acc[j][1], wj, xp1);
                ffma2(acc[j][2], wj, xp2);
                ffma2(acc[j][3], wj, xp3);
            }
        }
    }

    __syncthreads();   // done reading wT; reuse region as esm

    // add bias, scatter accumulators into epilogue tile esm[hw][o]
    float bias[OT];
    #pragma unroll
    for (int j = 0; j < OT; j++) {
        int o = obase + j;
        bias[j] = (o < NCLS*AA) ? cls_b[o] : reg_b[o - NCLS*AA];
    }
    #pragma unroll
    for (int j = 0; j < OT; j++)
        #pragma unroll
        for (int p = 0; p < NPAIR; p++) {
            float2 v = unpack2(acc[j][p]);
            int m0 = 2*lane + 64*p;
            esm[(m0    )*ESM_STRIDE + obase + j] = v.x + bias[j];
            esm[(m0 + 1)*ESM_STRIDE + obase + j] = v.y + bias[j];
        }
    __syncthreads();

    // per-anchor epilogue: softmax + decode + store + warp-aggregated histogram
    for (int t = tid; t < TILE_HW*AA; t += NTHREADS) {
        int hwl = t / AA;
        int a   = t - hwl*AA;
        if (hw0 + hwl >= HWTOT) continue;
        int n = (hw0 + hwl)*AA + a;                 // anchor index within batch
        const float* e = esm + hwl*ESM_STRIDE;

        // softmax over 4 class logits (channel o = a*4 + c)
        float l0 = e[a*4+0], l1 = e[a*4+1], l2 = e[a*4+2], l3 = e[a*4+3];
        float m  = fmaxf(fmaxf(l0, l1), fmaxf(l2, l3));
        float e0 = expf(l0 - m), e1 = expf(l1 - m), e2 = expf(l2 - m), e3 = expf(l3 - m);
        float inv = 1.f / (e0 + e1 + e2 + e3);
        float p0 = e0*inv, p1 = e1*inv, p2 = e2*inv, p3 = e3*inv;

        size_t base = (size_t)b*NANCH + n;
        *(float4*)(g_scores + base*4) = make_float4(p0, p1, p2, p3);
        float mx = fmaxf(fmaxf(p1, p2), p3);
        g_maxs[base] = mx;

        // warp-aggregated histogram update
        unsigned bin  = __float_as_uint(mx) >> 16;
        unsigned amask = __activemask();
        unsigned peers = __match_any_sync(amask, bin);
        int leader = __ffs(peers) - 1;
        if ((tid & 31) == leader)
            atomicAdd(&g_hist[b*NBINS + bin], (unsigned)__popc(peers));

        // decode; padded stride-8 vector stores
        const float* d  = e + NCLS*AA + a*NREG;
        const float* an = anchors + (size_t)n*NREG;
        float xa = an[0], ya = an[1], za = an[2];
        float dxa = an[3], dya = an[4], dza = an[5], ra = an[6];
        float diag = sqrtf(dxa*dxa + dya*dya);
        float* ob = g_boxes + base*BOXSTRIDE;
        float4 b0, b1;
        b0.x = fmaf(d[0], diag, xa);
        b0.y = fmaf(d[1], diag, ya);
        b0.z = fmaf(d[2], dza,  za);
        b0.w = expf(d[3]) * dxa;
        b1.x = expf(d[4]) * dya;
        b1.y = expf(d[5]) * dza;
        b1.z = d[6] + ra;
        b1.w = 0.f;
        *(float4*)(ob + 0) = b0;
        *(float4*)(ob + 4) = b1;
    }
}

// ============================================================================
// Stage 2a: per-batch threshold find from the histogram
// ============================================================================
__global__ __launch_bounds__(1024)
void threshold_kernel()
{
    const int b    = blockIdx.x;
    const int tid  = threadIdx.x;
    const int lane = tid & 31;
    const int wrp  = tid >> 5;

    __shared__ unsigned csum[1024];
    __shared__ unsigned wsum[32];

    const unsigned* h = g_hist + b*NBINS;
    {
        const uint4* h4 = (const uint4*)(h + tid*64);
        unsigned s = 0;
        #pragma unroll
        for (int k = 0; k < 16; k++) { uint4 v = h4[k]; s += v.x + v.y + v.z + v.w; }
        csum[tid] = s;
        unsigned ws = s;
        #pragma unroll
        for (int o = 16; o > 0; o >>= 1) ws += __shfl_down_sync(0xFFFFFFFFu, ws, o);
        if (lane == 0) wsum[wrp] = ws;
    }
    __syncthreads();

    if (tid == 0) {
        unsigned cum = 0;
        int w = 31;
        for (; w > 0; w--) { if (cum + wsum[w] >= (unsigned)KTOP) break; cum += wsum[w]; }
        int t = w*32 + 31;
        for (; t > w*32; t--) { if (cum + csum[t] >= (unsigned)KTOP) break; cum += csum[t]; }
        int thr = t*64;
        for (int k = 63; k >= 0; k--) {
            unsigned c = h[t*64 + k];
            if (cum + c >= (unsigned)KTOP) { thr = t*64 + k; break; }
            cum += c;
        }
        g_thr[b] = thr;
        g_candCnt[b] = 0;
    }
}

// ============================================================================
// Stage 2b: chip-wide candidate compaction + histogram re-zero
// grid = (CBLK, BB); runs after threshold_kernel (stream order).
// ============================================================================
__global__ __launch_bounds__(512)
void compact_kernel()
{
    const int b   = blockIdx.y;
    const int blk = blockIdx.x;
    const int tid = threadIdx.x;

    // re-zero this block's slice of the histogram (already consumed)
    {
        uint4* h4 = (uint4*)(g_hist + b*NBINS + blk*(NBINS/CBLK));
        if (tid < (NBINS/CBLK)/4) h4[tid] = make_uint4(0u,0u,0u,0u);
    }

    const int thr = g_thr[b];
    const float* mv = g_maxs + (size_t)b*NANCH;
    const int i0 = blk * CSLICE;
    for (int i = i0 + tid; i < i0 + CSLICE; i += 512) {
        float v = mv[i];
        if ((int)(__float_as_uint(v) >> 16) >= thr) {
            int p = atomicAdd(&g_candCnt[b], 1);
            if (p < CANDMAX) { g_candV[b*CANDMAX + p] = v; g_candI[b*CANDMAX + p] = i; }
        }
    }
}

// ============================================================================
// Stage 2c: per-batch sort + gather
// ============================================================================
__global__ __launch_bounds__(1024)
void sort_kernel(float* __restrict__ outS, float* __restrict__ outB)
{
    const int b   = blockIdx.x;
    const int tid = threadIdx.x;

    __shared__ float sv[CANDMAX];
    __shared__ int   si[CANDMAX];

    int cnt = g_candCnt[b];
    if (cnt > CANDMAX) cnt = CANDMAX;
    int p2 = 128;
    while (p2 < cnt) p2 <<= 1;

    for (int k = tid; k < p2; k += 1024) {
        if (k < cnt) { sv[k] = g_candV[b*CANDMAX + k]; si[k] = g_candI[b*CANDMAX + k]; }
        else         { sv[k] = -FLT_MAX;               si[k] = 0x7FFFFFFF; }
    }
    __syncthreads();

    // bitonic sort desc by (value, then ascending index)
    for (int k2 = 2; k2 <= p2; k2 <<= 1) {
        for (int j = k2 >> 1; j > 0; j >>= 1) {
            for (int i = tid; i < p2; i += 1024) {
                int ixj = i ^ j;
                if (ixj > i) {
                    float va = sv[i], vb = sv[ixj];
                    int   ia = si[i], ib = si[ixj];
                    bool a_below_b = (va < vb) || (va == vb && ia > ib);
                    bool up = ((i & k2) == 0);
                    if (up ? a_below_b : !a_below_b) {
                        sv[i] = vb; sv[ixj] = va; si[i] = ib; si[ixj] = ia;
                    }
                }
            }
            __syncthreads();
        }
    }

    if (tid < KTOP) {
        int k = tid;
        int n = si[k];
        size_t base = (size_t)b*NANCH + n;
        float4 s4 = *(const float4*)(g_scores + base*4);
        *(float4*)(outS + ((size_t)b*KTOP + k)*4) = s4;
        const float* bx = g_boxes + base*BOXSTRIDE;
        float4 b0 = *(const float4*)(bx + 0);
        float4 b1 = *(const float4*)(bx + 4);
        float* ob = outB + ((size_t)b*KTOP + k)*NREG;
        ob[0] = b0.x; ob[1] = b0.y; ob[2] = b0.z; ob[3] = b0.w;
        ob[4] = b1.x; ob[5] = b1.y; ob[6] = b1.z;
    }
}

// ============================================================================
extern "C" void kernel_launch(void* const* d_in, const int* in_sizes, int n_in,
                              void* d_out, int out_size)
{
    const float* x       = (const float*)d_in[0];
    const float* cls_w   = (const float*)d_in[1];
    const float* cls_b   = (const float*)d_in[2];
    const float* reg_w   = (const float*)d_in[3];
    const float* reg_b   = (const float*)d_in[4];
    const float* anchors = (const float*)d_in[5];

    float* outS = (float*)d_out;                 // [B, K, 4]
    float* outB = outS + (size_t)BB*KTOP*NCLS;   // [B, K, 7]

    cudaFuncSetAttribute(head_kernel, cudaFuncAttributeMaxDynamicSharedMemorySize, SMEM_BYTES);

    head_kernel<<<dim3((HWTOT + TILE_HW - 1)/TILE_HW, BB), NTHREADS, SMEM_BYTES>>>(
        x, cls_w, cls_b, reg_w, reg_b, anchors);
    threshold_kernel<<<BB, 1024>>>();
    compact_kernel<<<dim3(CBLK, BB), 512>>>();
    sort_kernel<<<BB, 1024>>>(outS, outB);
}

// round 15
// speedup vs baseline: 1.2257x; 1.0359x over previous
#include <cuda_runtime.h>
#include <math.h>
#include <float.h>
#include <stdint.h>

// ---------------- problem constants ----------------
#define BB     4
#define CIN    256
#define HH     200
#define WW     176
#define HWTOT  (HH*WW)          // 35200
#define AA     6
#define NCLS   4
#define NREG   7
#define NCLSCH (NCLS*AA)        // 24 cls channels
#define NOUT   (NCLS*AA + NREG*AA)   // 66
#define NANCH  (AA*HWTOT)       // 211200
#define KTOP   100

// ---------------- stage-1 tiling (cls-only head) ----------------
#define TILE_HW  256
#define CK       16
#define NITER    (CIN/CK)       // 16
#define NTHREADS 256            // 8 warps
#define OT       3              // outputs per warp (8*3 = 24)
#define NPAIR    4              // hw pairs per thread
#define ESM_STRIDE 25           // epilogue row stride (24 + 1)
// smem floats: wT [0,6144) | xsA [6144,10240) | xsB [10240,14336)
// esm overlays xsA+xsB at 6144 (needs 256*25=6400 <= 8192)
#define SM_WT    0
#define SM_XSA   6144
#define SM_XSB   10240
#define SM_ESM   6144
#define SMEM_FLOATS 14336
#define SMEM_BYTES  (SMEM_FLOATS*4)   // 57344
#define CHUNK_FLOATS (CK*TILE_HW)     // 4096
#define CHUNK_F4 (CHUNK_FLOATS/4)     // 1024

// ---------------- top-k constants ----------------
#define NBINS   65536
#define CANDMAX 4096
#define CBLK    32
#define CSLICE  (NANCH/CBLK)    // 6600

// ---------------- gather smem (floats) ----------------
#define G_WT    0                 // [256][68]
#define G_BIAS  (256*68)          // 17408, 68 floats
#define G_XCOL  (G_BIAS + 68)     // [8][256]
#define G_CHAN  (G_XCOL + 8*256)  // [8][68]
#define G_FLOATS (G_CHAN + 8*68)
#define G_BYTES  (G_FLOATS*4)     // ~80 KB

// ---------------- device scratch (zero-initialized at module load) ----------------
__device__ float    g_maxs  [(size_t)BB*NANCH];
__device__ unsigned g_hist  [BB*NBINS];   // re-zeroed by compact_kernel each run
__device__ int      g_thr   [BB];
__device__ int      g_candCnt[BB];
__device__ float    g_candV [BB*CANDMAX];
__device__ int      g_candI [BB*CANDMAX];
__device__ int      g_topI  [BB*KTOP];

// ---------------- cp.async helpers ----------------
__device__ __forceinline__ void cp16(uint32_t smem_addr, const void* gptr) {
    asm volatile("cp.async.ca.shared.global [%0], [%1], 16;"
                 :: "r"(smem_addr), "l"(gptr));
}
__device__ __forceinline__ void cp_commit() {
    asm volatile("cp.async.commit_group;");
}
template<int N> __device__ __forceinline__ void cp_wait() {
    asm volatile("cp.async.wait_group %0;" :: "n"(N));
}

// ---------------- packed f32x2 helpers ----------------
__device__ __forceinline__ void ffma2(unsigned long long& d,
                                      unsigned long long a,
                                      unsigned long long b) {
    asm("fma.rn.f32x2 %0, %1, %2, %0;" : "+l"(d) : "l"(a), "l"(b));
}
__device__ __forceinline__ unsigned long long pack_dup(float w) {
    unsigned long long r;
    asm("mov.b64 %0, {%1, %1};" : "=l"(r) : "f"(w));
    return r;
}
__device__ __forceinline__ float2 unpack2(unsigned long long v) {
    float2 f;
    asm("mov.b64 {%0, %1}, %2;" : "=f"(f.x), "=f"(f.y) : "l"(v));
    return f;
}

// ============================================================================
// Stage 1: cls-only head (GEMM 24ch via FFMA2) + softmax-max + histogram
// ============================================================================
__global__ __launch_bounds__(NTHREADS, 3)
void head_kernel(const float* __restrict__ x,
                 const float* __restrict__ cls_w, const float* __restrict__ cls_b)
{
    extern __shared__ float sm[];
    float* wT  = sm + SM_WT;      // [256][24]
    float* xsA = sm + SM_XSA;
    float* xsB = sm + SM_XSB;
    float* esm = sm + SM_ESM;     // [256][25], overlays xs after GEMM

    const int b    = blockIdx.y;
    const int hw0  = blockIdx.x * TILE_HW;
    const int tid  = threadIdx.x;
    const int lane = tid & 31;
    const int wrp  = tid >> 5;       // 0..7
    const int obase = wrp * OT;      // 0..21

    const float* xb = x + (size_t)b * CIN * HWTOT;
    const uint32_t xsA_s = (uint32_t)__cvta_generic_to_shared(xsA);
    const uint32_t xsB_s = (uint32_t)__cvta_generic_to_shared(xsB);

    auto issue_chunk = [&](int cc, float* dst, uint32_t dst_s) {
        for (int idx = tid; idx < CHUNK_F4; idx += NTHREADS) {
            int c   = idx >> 6;
            int f4  = idx & 63;
            int col = f4 * 4;
            if (hw0 + col < HWTOT) {
                cp16(dst_s + (uint32_t)(c*TILE_HW + col)*4,
                     xb + (size_t)(cc + c)*HWTOT + hw0 + col);
            } else {
                *(float4*)(dst + c*TILE_HW + col) = make_float4(0.f,0.f,0.f,0.f);
            }
        }
        cp_commit();
    };

    issue_chunk(0, xsA, xsA_s);

    // cls weights transposed: wT[c*24 + o]
    for (int idx = tid; idx < NCLSCH*CIN; idx += NTHREADS) {
        int o = idx >> 8;
        int c = idx & 255;
        wT[c*NCLSCH + o] = cls_w[o*CIN + c];
    }

    unsigned long long acc[OT][NPAIR];
    #pragma unroll
    for (int j = 0; j < OT; j++)
        #pragma unroll
        for (int p = 0; p < NPAIR; p++) acc[j][p] = 0ull;

    #pragma unroll 1
    for (int it = 0; it < NITER; it++) {
        const int cc = it * CK;
        float* cur = (it & 1) ? xsB : xsA;
        if (it + 1 < NITER) {
            if (it > 0) __syncthreads();
            float*   nxt   = (it & 1) ? xsA : xsB;
            uint32_t nxt_s = (it & 1) ? xsA_s : xsB_s;
            issue_chunk(cc + CK, nxt, nxt_s);
            cp_wait<1>();
        } else {
            cp_wait<0>();
        }
        __syncthreads();

        #pragma unroll
        for (int c = 0; c < CK; c++) {
            unsigned long long xp0 = *(const unsigned long long*)(cur + c*TILE_HW + 2*lane);
            unsigned long long xp1 = *(const unsigned long long*)(cur + c*TILE_HW + 2*lane + 64);
            unsigned long long xp2 = *(const unsigned long long*)(cur + c*TILE_HW + 2*lane + 128);
            unsigned long long xp3 = *(const unsigned long long*)(cur + c*TILE_HW + 2*lane + 192);
            const float* wrow = &wT[(cc + c)*NCLSCH + obase];
            #pragma unroll
            for (int j = 0; j < OT; j++) {
                unsigned long long wj = pack_dup(wrow[j]);
                ffma2(acc[j][0], wj, xp0);
                ffma2(acc[j][1], wj, xp1);
                ffma2(acc[j][2], wj, xp2);
                ffma2(acc[j][3], wj, xp3);
            }
        }
    }

    __syncthreads();   // GEMM reads done; reuse xs region as esm

    float bias[OT];
    #pragma unroll
    for (int j = 0; j < OT; j++) bias[j] = cls_b[obase + j];
    #pragma unroll
    for (int j = 0; j < OT; j++)
        #pragma unroll
        for (int p = 0; p < NPAIR; p++) {
            float2 v = unpack2(acc[j][p]);
            int m0 = 2*lane + 64*p;
            esm[(m0    )*ESM_STRIDE + obase + j] = v.x + bias[j];
            esm[(m0 + 1)*ESM_STRIDE + obase + j] = v.y + bias[j];
        }
    __syncthreads();

    // per-anchor: softmax -> max fg prob -> g_maxs + histogram
    for (int t = tid; t < TILE_HW*AA; t += NTHREADS) {
        int hwl = t / AA;
        int a   = t - hwl*AA;
        if (hw0 + hwl >= HWTOT) continue;
        int n = (hw0 + hwl)*AA + a;
        const float* e = esm + hwl*ESM_STRIDE;

        float l0 = e[a*4+0], l1 = e[a*4+1], l2 = e[a*4+2], l3 = e[a*4+3];
        float m  = fmaxf(fmaxf(l0, l1), fmaxf(l2, l3));
        float e0 = expf(l0 - m), e1 = expf(l1 - m), e2 = expf(l2 - m), e3 = expf(l3 - m);
        float inv = 1.f / (e0 + e1 + e2 + e3);
        float mx = fmaxf(fmaxf(e1, e2), e3) * inv;

        g_maxs[(size_t)b*NANCH + n] = mx;

        unsigned bin  = __float_as_uint(mx) >> 16;
        unsigned amask = __activemask();
        unsigned peers = __match_any_sync(amask, bin);
        int leader = __ffs(peers) - 1;
        if ((tid & 31) == leader)
            atomicAdd(&g_hist[b*NBINS + bin], (unsigned)__popc(peers));
    }
}

// ============================================================================
// Stage 2a: per-batch threshold find
// ============================================================================
__global__ __launch_bounds__(1024)
void threshold_kernel()
{
    const int b    = blockIdx.x;
    const int tid  = threadIdx.x;
    const int lane = tid & 31;
    const int wrp  = tid >> 5;

    __shared__ unsigned csum[1024];
    __shared__ unsigned wsum[32];

    const unsigned* h = g_hist + b*NBINS;
    {
        const uint4* h4 = (const uint4*)(h + tid*64);
        unsigned s = 0;
        #pragma unroll
        for (int k = 0; k < 16; k++) { uint4 v = h4[k]; s += v.x + v.y + v.z + v.w; }
        csum[tid] = s;
        unsigned ws = s;
        #pragma unroll
        for (int o = 16; o > 0; o >>= 1) ws += __shfl_down_sync(0xFFFFFFFFu, ws, o);
        if (lane == 0) wsum[wrp] = ws;
    }
    __syncthreads();

    if (tid == 0) {
        unsigned cum = 0;
        int w = 31;
        for (; w > 0; w--) { if (cum + wsum[w] >= (unsigned)KTOP) break; cum += wsum[w]; }
        int t = w*32 + 31;
        for (; t > w*32; t--) { if (cum + csum[t] >= (unsigned)KTOP) break; cum += csum[t]; }
        int thr = t*64;
        for (int k = 63; k >= 0; k--) {
            unsigned c = h[t*64 + k];
            if (cum + c >= (unsigned)KTOP) { thr = t*64 + k; break; }
            cum += c;
        }
        g_thr[b] = thr;
        g_candCnt[b] = 0;
    }
}

// ============================================================================
// Stage 2b: chip-wide compaction + hist re-zero
// ============================================================================
__global__ __launch_bounds__(512)
void compact_kernel()
{
    const int b   = blockIdx.y;
    const int blk = blockIdx.x;
    const int tid = threadIdx.x;

    {
        uint4* h4 = (uint4*)(g_hist + b*NBINS + blk*(NBINS/CBLK));
        if (tid < (NBINS/CBLK)/4) h4[tid] = make_uint4(0u,0u,0u,0u);
    }

    const int thr = g_thr[b];
    const float* mv = g_maxs + (size_t)b*NANCH;
    const int i0 = blk * CSLICE;
    for (int i = i0 + tid; i < i0 + CSLICE; i += 512) {
        float v = mv[i];
        if ((int)(__float_as_uint(v) >> 16) >= thr) {
            int p = atomicAdd(&g_candCnt[b], 1);
            if (p < CANDMAX) { g_candV[b*CANDMAX + p] = v; g_candI[b*CANDMAX + p] = i; }
        }
    }
}

// ============================================================================
// Stage 2c: per-batch sort -> sorted top-K indices
// ============================================================================
__global__ __launch_bounds__(1024)
void sort_kernel()
{
    const int b   = blockIdx.x;
    const int tid = threadIdx.x;

    __shared__ float sv[CANDMAX];
    __shared__ int   si[CANDMAX];

    int cnt = g_candCnt[b];
    if (cnt > CANDMAX) cnt = CANDMAX;
    int p2 = 128;
    while (p2 < cnt) p2 <<= 1;

    for (int k = tid; k < p2; k += 1024) {
        if (k < cnt) { sv[k] = g_candV[b*CANDMAX + k]; si[k] = g_candI[b*CANDMAX + k]; }
        else         { sv[k] = -FLT_MAX;               si[k] = 0x7FFFFFFF; }
    }
    __syncthreads();

    for (int k2 = 2; k2 <= p2; k2 <<= 1) {
        for (int j = k2 >> 1; j > 0; j >>= 1) {
            for (int i = tid; i < p2; i += 1024) {
                int ixj = i ^ j;
                if (ixj > i) {
                    float va = sv[i], vb = sv[ixj];
                    int   ia = si[i], ib = si[ixj];
                    bool a_below_b = (va < vb) || (va == vb && ia > ib);
                    bool up = ((i & k2) == 0);
                    if (up ? a_below_b : !a_below_b) {
                        sv[i] = vb; sv[ixj] = va; si[i] = ib; si[ixj] = ia;
                    }
                }
            }
            __syncthreads();
        }
    }

    if (tid < KTOP) g_topI[b*KTOP + tid] = si[tid];
}

// ============================================================================
// Stage 3: gather — recompute all 66 channels for top-K anchors only,
// then softmax + decode + write outputs. grid (4, BB), 256 threads.
// ============================================================================
__global__ __launch_bounds__(256)
void gather_kernel(float* __restrict__ outS, float* __restrict__ outB,
                   const float* __restrict__ x,
                   const float* __restrict__ cls_w, const float* __restrict__ cls_b,
                   const float* __restrict__ reg_w, const float* __restrict__ reg_b,
                   const float* __restrict__ anchors)
{
    extern __shared__ float gs[];
    float* wt   = gs + G_WT;     // [k][68] transposed weights
    float* sb   = gs + G_BIAS;   // 66 biases
    float* xcol = gs + G_XCOL;   // per-warp x column [8][256]
    float* chan = gs + G_CHAN;   // per-warp channel results [8][68]

    const int b    = blockIdx.y;
    const int part = blockIdx.x;    // 0..3, 25 anchors each
    const int tid  = threadIdx.x;
    const int lane = tid & 31;
    const int wrp  = tid >> 5;      // 0..7

    // load transposed weights: wt[k*68 + o]
    for (int idx = tid; idx < NOUT*CIN; idx += 256) {
        int o = idx >> 8;
        int k = idx & 255;
        float v = (o < NCLSCH) ? cls_w[o*CIN + k] : reg_w[(o - NCLSCH)*CIN + k];
        wt[k*68 + o] = v;
    }
    if (tid < NOUT)
        sb[tid] = (tid < NCLSCH) ? cls_b[tid] : reg_b[tid - NCLSCH];
    __syncthreads();

    const float* xb = x + (size_t)b * CIN * HWTOT;

    #pragma unroll 1
    for (int it = 0; it < 4; it++) {
        int kloc = it*8 + wrp;            // 0..31
        int kk   = part*25 + kloc;        // global rank
        bool valid = (kloc < 25) && (kk < KTOP);
        int n = 0, hw = 0, a = 0;
        if (valid) {
            n  = g_topI[b*KTOP + kk];
            hw = n / AA;
            a  = n - hw*AA;
        }
        if (valid) {
            for (int c = lane; c < CIN; c += 32)
                xcol[wrp*256 + c] = xb[(size_t)c*HWTOT + hw];
        }
        __syncwarp();
        if (valid) {
            for (int o = lane; o < NOUT; o += 32) {
                float s = sb[o];
                const float* wp = wt + o;
                const float* xc = xcol + wrp*256;
                #pragma unroll 8
                for (int k = 0; k < CIN; k++) s = fmaf(wp[k*68], xc[k], s);
                chan[wrp*68 + o] = s;
            }
        }
        __syncwarp();
        if (valid && lane == 0) {
            const float* ch = chan + wrp*68;
            float l0 = ch[a*4+0], l1 = ch[a*4+1], l2 = ch[a*4+2], l3 = ch[a*4+3];
            float m  = fmaxf(fmaxf(l0, l1), fmaxf(l2, l3));
            float e0 = expf(l0-m), e1 = expf(l1-m), e2 = expf(l2-m), e3 = expf(l3-m);
            float inv = 1.f / (e0 + e1 + e2 + e3);
            float* os = outS + ((size_t)b*KTOP + kk)*NCLS;
            os[0] = e0*inv; os[1] = e1*inv; os[2] = e2*inv; os[3] = e3*inv;

            const float* d  = ch + NCLSCH + a*NREG;
            const float* an = anchors + (size_t)n*NREG;
            float xa = an[0], ya = an[1], za = an[2];
            float dxa = an[3], dya = an[4], dza = an[5], ra = an[6];
            float diag = sqrtf(dxa*dxa + dya*dya);
            float* ob = outB + ((size_t)b*KTOP + kk)*NREG;
            ob[0] = fmaf(d[0], diag, xa);
            ob[1] = fmaf(d[1], diag, ya);
            ob[2] = fmaf(d[2], dza,  za);
            ob[3] = expf(d[3]) * dxa;
            ob[4] = expf(d[4]) * dya;
            ob[5] = expf(d[5]) * dza;
            ob[6] = d[6] + ra;
        }
        __syncwarp();   // xcol/chan reuse next iteration
    }
}

// ============================================================================
extern "C" void kernel_launch(void* const* d_in, const int* in_sizes, int n_in,
                              void* d_out, int out_size)
{
    const float* x       = (const float*)d_in[0];
    const float* cls_w   = (const float*)d_in[1];
    const float* cls_b   = (const float*)d_in[2];
    const float* reg_w   = (const float*)d_in[3];
    const float* reg_b   = (const float*)d_in[4];
    const float* anchors = (const float*)d_in[5];

    float* outS = (float*)d_out;                 // [B, K, 4]
    float* outB = outS + (size_t)BB*KTOP*NCLS;   // [B, K, 7]

    cudaFuncSetAttribute(head_kernel, cudaFuncAttributeMaxDynamicSharedMemorySize, SMEM_BYTES);
    cudaFuncSetAttribute(gather_kernel, cudaFuncAttributeMaxDynamicSharedMemorySize, G_BYTES);

    head_kernel<<<dim3((HWTOT + TILE_HW - 1)/TILE_HW, BB), NTHREADS, SMEM_BYTES>>>(
        x, cls_w, cls_b);
    threshold_kernel<<<BB, 1024>>>();
    compact_kernel<<<dim3(CBLK, BB), 512>>>();
    sort_kernel<<<BB, 1024>>>();
    gather_kernel<<<dim3(4, BB), 256, G_BYTES>>>(outS, outB, x, cls_w, cls_b,
                                                 reg_w, reg_b, anchors);
}